// round 3
// baseline (speedup 1.0000x reference)
#include <cuda_runtime.h>
#include <math.h>

// B=1, N=50000, K=32, D=128, fp32
#define D_DIM 128
#define K_NBR 32
#define THREADS 128

__global__ __launch_bounds__(THREADS, 10)
void attn_encoder_kernel(const float* __restrict__ h_n,
                         const float* __restrict__ neighbor,
                         float* __restrict__ out)
{
    __shared__ float  sc_sh[K_NBR];     // raw scores
    __shared__ float4 h_sh4[32];        // h_n tile (512 B)
    __shared__ float4 red4[4 * 32];     // per-warp partial aggregates (2 KB)

    const unsigned tid  = threadIdx.x;
    const unsigned w    = tid >> 5;     // warp: owns neighbors 8w..8w+7
    const unsigned lane = tid & 31;     // lane: owns float4 d-chunk [4*lane, 4*lane+3]
    const unsigned node = blockIdx.x;

    // ---- Load h (every warp loads; 3 of 4 are L1 hits). Warp 0 caches to smem. ----
    const float4 hv = reinterpret_cast<const float4*>(h_n)[node * 32u + lane];
    if (w == 0) h_sh4[lane] = hv;

    // ---- Load this warp's 8 neighbor rows straight into registers ----
    const float4* nbp = reinterpret_cast<const float4*>(neighbor)
                      + node * (unsigned)(K_NBR * D_DIM / 4) + (w * 8u) * (D_DIM / 4) + lane;
    float4 nb[8];
    #pragma unroll
    for (int kk = 0; kk < 8; ++kk)
        nb[kk] = nbp[kk * (D_DIM / 4)];          // 8 independent coalesced LDG.128

    // ---- Scores: dot(h, nb_k), butterfly-reduce, lane kk writes score ----
    #pragma unroll
    for (int kk = 0; kk < 8; ++kk) {
        float p = fmaf(nb[kk].x, hv.x,
                  fmaf(nb[kk].y, hv.y,
                  fmaf(nb[kk].z, hv.z, nb[kk].w * hv.w)));
        #pragma unroll
        for (int off = 16; off > 0; off >>= 1)
            p += __shfl_xor_sync(0xffffffffu, p, off);
        if (lane == (unsigned)kk)
            sc_sh[w * 8u + kk] = p * 0.08838834764831845f;   // 1/sqrt(128)
    }
    __syncthreads();

    // ---- Softmax over 32 scores, computed redundantly in EVERY warp ----
    const float s = sc_sh[lane];
    float m = s;
    #pragma unroll
    for (int off = 16; off > 0; off >>= 1)
        m = fmaxf(m, __shfl_xor_sync(0xffffffffu, m, off));
    const float e = __expf(s - m);
    float sum = e;
    #pragma unroll
    for (int off = 16; off > 0; off >>= 1)
        sum += __shfl_xor_sync(0xffffffffu, sum, off);
    const float at = e / sum;            // lane holds attn[lane]

    // ---- Aggregate this warp's 8 neighbors in registers ----
    float4 acc = make_float4(0.f, 0.f, 0.f, 0.f);
    #pragma unroll
    for (int kk = 0; kk < 8; ++kk) {
        const float a = __shfl_sync(0xffffffffu, at, w * 8u + kk);
        acc.x = fmaf(a, nb[kk].x, acc.x);
        acc.y = fmaf(a, nb[kk].y, acc.y);
        acc.z = fmaf(a, nb[kk].z, acc.z);
        acc.w = fmaf(a, nb[kk].w, acc.w);
    }
    red4[w * 32u + lane] = acc;          // conflict-free STS.128
    __syncthreads();

    // ---- Warp 0: cross-warp sum + residual, vectorized store ----
    if (w == 0) {
        const float4 r0 = red4[lane];
        const float4 r1 = red4[32 + lane];
        const float4 r2 = red4[64 + lane];
        const float4 r3 = red4[96 + lane];
        const float4 h  = h_sh4[lane];
        float4 o;
        o.x = h.x + r0.x + r1.x + r2.x + r3.x;
        o.y = h.y + r0.y + r1.y + r2.y + r3.y;
        o.z = h.z + r0.z + r1.z + r2.z + r3.z;
        o.w = h.w + r0.w + r1.w + r2.w + r3.w;
        reinterpret_cast<float4*>(out)[node * 32u + lane] = o;
    }
}

extern "C" void kernel_launch(void* const* d_in, const int* in_sizes, int n_in,
                              void* d_out, int out_size)
{
    const float* h_n      = (const float*)d_in[0];   // (B,N,D)
    const float* neighbor = (const float*)d_in[1];   // (B,N,K,D)
    float* out = (float*)d_out;

    const int n_nodes = in_sizes[0] / D_DIM;  // B*N = 50000

    attn_encoder_kernel<<<n_nodes, THREADS>>>(h_n, neighbor, out);
}

// round 4
// speedup vs baseline: 1.2060x; 1.2060x over previous
#include <cuda_runtime.h>
#include <math.h>

// B=1, N=50000, K=32, D=128, fp32
#define D_DIM   128
#define K_NBR   32
#define THREADS 256
#define NODES_PER_CTA 8   // one node per warp

__global__ __launch_bounds__(THREADS)
void attn_encoder_kernel(const float* __restrict__ h_n,
                         const float* __restrict__ neighbor,
                         float* __restrict__ out,
                         int n_nodes)
{
    const unsigned w    = threadIdx.x >> 5;
    const unsigned lane = threadIdx.x & 31;
    const unsigned node = blockIdx.x * NODES_PER_CTA + w;
    if (node >= (unsigned)n_nodes) return;

    // lane owns float4 d-chunk [4*lane, 4*lane+3]
    const float4 hv = reinterpret_cast<const float4*>(h_n)[node * 32u + lane];

    const float4* nbp = reinterpret_cast<const float4*>(neighbor)
                      + (size_t)node * (K_NBR * D_DIM / 4) + lane;

    float  m   = -INFINITY;
    float  sum = 0.f;
    float4 acc = make_float4(0.f, 0.f, 0.f, 0.f);

    #pragma unroll
    for (int c = 0; c < K_NBR / 8; ++c) {
        // ---- 8 independent coalesced LDG.128 ----
        float4 nb[8];
        #pragma unroll
        for (int j = 0; j < 8; ++j)
            nb[j] = nbp[(c * 8 + j) * (D_DIM / 4)];

        // ---- 8 dots + butterfly reductions (all lanes end with full sum) ----
        float s[8];
        #pragma unroll
        for (int j = 0; j < 8; ++j) {
            float p = fmaf(nb[j].x, hv.x,
                      fmaf(nb[j].y, hv.y,
                      fmaf(nb[j].z, hv.z, nb[j].w * hv.w)));
            #pragma unroll
            for (int off = 16; off > 0; off >>= 1)
                p += __shfl_xor_sync(0xffffffffu, p, off);
            s[j] = p * 0.08838834764831845f;   // 1/sqrt(128)
        }

        // ---- online softmax accumulator updates ----
        #pragma unroll
        for (int j = 0; j < 8; ++j) {
            const float mn   = fmaxf(m, s[j]);
            const float corr = __expf(m - mn);      // exp(-inf)=0 handles first iter
            const float p    = __expf(s[j] - mn);
            sum   = fmaf(sum, corr, p);
            acc.x = fmaf(p, nb[j].x, acc.x * corr);
            acc.y = fmaf(p, nb[j].y, acc.y * corr);
            acc.z = fmaf(p, nb[j].z, acc.z * corr);
            acc.w = fmaf(p, nb[j].w, acc.w * corr);
            m = mn;
        }
    }

    // ---- normalize, residual, coalesced store ----
    const float inv = __frcp_rn(sum);
    float4 o;
    o.x = fmaf(acc.x, inv, hv.x);
    o.y = fmaf(acc.y, inv, hv.y);
    o.z = fmaf(acc.z, inv, hv.z);
    o.w = fmaf(acc.w, inv, hv.w);
    reinterpret_cast<float4*>(out)[node * 32u + lane] = o;
}

extern "C" void kernel_launch(void* const* d_in, const int* in_sizes, int n_in,
                              void* d_out, int out_size)
{
    const float* h_n      = (const float*)d_in[0];   // (B,N,D)
    const float* neighbor = (const float*)d_in[1];   // (B,N,K,D)
    float* out = (float*)d_out;

    const int n_nodes = in_sizes[0] / D_DIM;         // B*N = 50000
    const int grid = (n_nodes + NODES_PER_CTA - 1) / NODES_PER_CTA;

    attn_encoder_kernel<<<grid, THREADS>>>(h_n, neighbor, out, n_nodes);
}